// round 1
// baseline (speedup 1.0000x reference)
#include <cuda_runtime.h>

#define B_  8
#define C_  64
#define O_  64
#define H_  160
#define W_  160
#define HW_ (H_*W_)
#define OCOFF 18
#define CK  576      // C_ * 9
#define PIX 32

// Scratch for the offset feature map [B,18,H,W]
__device__ float g_offset[B_ * OCOFF * HW_];

// ---------------------------------------------------------------------------
// Kernel 1: 3x3 offset conv (pad 1): x[B,64,H,W] -> g_offset[B,18,H,W]
// Block: 144 threads, 32-pixel row tile. im2col staged transposed in smem,
// 2o x 2p register tile, weights via __ldg (L1/L2 resident, 41 KB).
// ---------------------------------------------------------------------------
__global__ __launch_bounds__(144) void offset_conv_kernel(
    const float* __restrict__ x,
    const float* __restrict__ w_off,
    const float* __restrict__ b_off)
{
    extern __shared__ float sm[];
    float* colsT = sm;                       // [576][32]

    const int b  = blockIdx.z;
    const int h  = blockIdx.y;
    const int w0 = blockIdx.x * PIX;
    const int tid = threadIdx.x;

    // im2col: colsT[(c*9+k)][p] = x[b,c,h+ky-1,w0+p+kx-1] (0 for OOB)
    for (int j = tid; j < CK * PIX; j += 144) {
        const int p   = j & 31;
        const int idx = j >> 5;
        const int c   = idx / 9;
        const int k   = idx - c * 9;
        const int row = h + (k / 3) - 1;
        const int col = w0 + p + (k % 3) - 1;
        float v = 0.0f;
        if (row >= 0 && row < H_ && col >= 0 && col < W_)
            v = __ldg(x + (b * C_ + c) * HW_ + row * W_ + col);
        colsT[idx * PIX + p] = v;
    }
    __syncthreads();

    const int og = tid / 16;        // 0..8  -> o in {2og, 2og+1}
    const int pg = tid - og * 16;   // 0..15 -> p in {2pg, 2pg+1}

    float a00 = 0.f, a01 = 0.f, a10 = 0.f, a11 = 0.f;
    const float4* w4 = (const float4*)w_off;    // [18][144] of float4
    const float2* c2 = (const float2*)colsT;    // [576][16] of float2

    #pragma unroll 4
    for (int ii = 0; ii < CK; ii += 4) {
        const float2 cv0 = c2[(ii + 0) * 16 + pg];
        const float2 cv1 = c2[(ii + 1) * 16 + pg];
        const float2 cv2 = c2[(ii + 2) * 16 + pg];
        const float2 cv3 = c2[(ii + 3) * 16 + pg];
        const float4 wa = __ldg(w4 + (2 * og + 0) * 144 + (ii >> 2));
        const float4 wb = __ldg(w4 + (2 * og + 1) * 144 + (ii >> 2));
        a00 += wa.x * cv0.x + wa.y * cv1.x + wa.z * cv2.x + wa.w * cv3.x;
        a01 += wa.x * cv0.y + wa.y * cv1.y + wa.z * cv2.y + wa.w * cv3.y;
        a10 += wb.x * cv0.x + wb.y * cv1.x + wb.z * cv2.x + wb.w * cv3.x;
        a11 += wb.x * cv0.y + wb.y * cv1.y + wb.z * cv2.y + wb.w * cv3.y;
    }

    const int o0 = 2 * og, o1 = 2 * og + 1;
    const float b0 = __ldg(b_off + o0);
    const float b1 = __ldg(b_off + o1);
    const int pbase = h * W_ + w0 + 2 * pg;
    float2 r0, r1;
    r0.x = a00 + b0; r0.y = a01 + b0;
    r1.x = a10 + b1; r1.y = a11 + b1;
    *(float2*)(&g_offset[(b * OCOFF + o0) * HW_ + pbase]) = r0;
    *(float2*)(&g_offset[(b * OCOFF + o1) * HW_ + pbase]) = r1;
}

// ---------------------------------------------------------------------------
// Kernel 2: deform sample + implicit GEMM (O=64, K=576) + BN + ReLU.
// Block: 128 threads, 32-pixel row tile.
//   Phase A: per-(p,k) bilinear tap metadata (shared over all c),
//            sample cols into smem transposed [i=c*9+k][p].
//   Phase B: 4o x 4p register-tiled GEMM, float4 smem loads, w via __ldg.
// ---------------------------------------------------------------------------
__global__ __launch_bounds__(128) void deform_main_kernel(
    const float* __restrict__ x,
    const float* __restrict__ w_dcn,
    const float* __restrict__ b_dcn,
    const float* __restrict__ gamma,
    const float* __restrict__ beta,
    const float* __restrict__ run_mean,
    const float* __restrict__ run_var,
    float* __restrict__ out)
{
    extern __shared__ float sm[];
    float* colsT = sm;                               // [576][32] = 18432 floats
    int*   ia    = (int*)(sm + CK * PIX);            // 4 x [288] int
    int*   a00s  = ia;
    int*   a01s  = ia + 288;
    int*   a10s  = ia + 576;
    int*   a11s  = ia + 864;
    float* wt    = sm + CK * PIX + 1152;             // 4 x [288] float
    float* w00s  = wt;
    float* w01s  = wt + 288;
    float* w10s  = wt + 576;
    float* w11s  = wt + 864;
    float* scale_s = sm + CK * PIX + 2304;           // [64]
    float* shift_s = scale_s + 64;                   // [64]

    const int b  = blockIdx.z;
    const int h  = blockIdx.y;
    const int w0 = blockIdx.x * PIX;
    const int tid = threadIdx.x;

    // BN scale/shift (b_dcn folded in): y = conv*inv + (b_dcn*inv + beta - mean*inv)
    if (tid < 64) {
        const float inv = __ldg(gamma + tid) * rsqrtf(__ldg(run_var + tid) + 1e-5f);
        scale_s[tid] = inv;
        shift_s[tid] = __ldg(beta + tid) + (__ldg(b_dcn + tid) - __ldg(run_mean + tid)) * inv;
    }

    // Tap metadata for 32 pixels x 9 kernel positions
    for (int j = tid; j < 9 * PIX; j += 128) {
        const int k = j >> 5;
        const int p = j & 31;
        const float offy = g_offset[(b * OCOFF + 2 * k)     * HW_ + h * W_ + w0 + p];
        const float offx = g_offset[(b * OCOFF + 2 * k + 1) * HW_ + h * W_ + w0 + p];
        const float py = (float)(h + k / 3 - 1) + offy;
        const float px = (float)(w0 + p + (k % 3) - 1) + offx;
        const float y0f = floorf(py);
        const float x0f = floorf(px);
        const float fy = py - y0f;
        const float fx = px - x0f;
        const int iy0 = (int)y0f, iy1 = iy0 + 1;
        const int ix0 = (int)x0f, ix1 = ix0 + 1;
        const bool vy0 = (iy0 >= 0) && (iy0 < H_);
        const bool vy1 = (iy1 >= 0) && (iy1 < H_);
        const bool vx0 = (ix0 >= 0) && (ix0 < W_);
        const bool vx1 = (ix1 >= 0) && (ix1 < W_);
        const float wy0 = 1.0f - fy, wy1 = fy;
        const float wx0 = 1.0f - fx, wx1 = fx;
        w00s[j] = (vy0 && vx0) ? wy0 * wx0 : 0.0f;
        w01s[j] = (vy0 && vx1) ? wy0 * wx1 : 0.0f;
        w10s[j] = (vy1 && vx0) ? wy1 * wx0 : 0.0f;
        w11s[j] = (vy1 && vx1) ? wy1 * wx1 : 0.0f;
        const int iy0c = min(max(iy0, 0), H_ - 1);
        const int iy1c = min(max(iy1, 0), H_ - 1);
        const int ix0c = min(max(ix0, 0), W_ - 1);
        const int ix1c = min(max(ix1, 0), W_ - 1);
        a00s[j] = iy0c * W_ + ix0c;
        a01s[j] = iy0c * W_ + ix1c;
        a10s[j] = iy1c * W_ + ix0c;
        a11s[j] = iy1c * W_ + ix1c;
    }
    __syncthreads();

    // Bilinear sampling into colsT[i][p]  (i = c*9+k, matches w_dcn.reshape(O, C*9))
    {
        const int p  = tid & 31;
        const int cg = tid >> 5;                   // 0..3
        const float* xb = x + b * C_ * HW_;
        #pragma unroll
        for (int k = 0; k < 9; k++) {
            const int j = k * 32 + p;
            const int i00 = a00s[j], i01 = a01s[j], i10 = a10s[j], i11 = a11s[j];
            const float w00 = w00s[j], w01 = w01s[j], w10 = w10s[j], w11 = w11s[j];
            #pragma unroll 4
            for (int c = cg; c < C_; c += 4) {
                const float* xc = xb + c * HW_;
                const float v = w00 * __ldg(xc + i00) + w01 * __ldg(xc + i01)
                              + w10 * __ldg(xc + i10) + w11 * __ldg(xc + i11);
                colsT[(c * 9 + k) * PIX + p] = v;
            }
        }
    }
    __syncthreads();

    // GEMM: out[32 pix][64 o] = colsT[576][32]^T x w[64][576]^T
    const int og = tid >> 3;        // 0..15 -> o base = 4*og
    const int pg = tid & 7;         // 0..7  -> p base = 4*pg
    float acc[4][4];
    #pragma unroll
    for (int i = 0; i < 4; i++)
        #pragma unroll
        for (int jj = 0; jj < 4; jj++) acc[i][jj] = 0.0f;

    const float4* w4 = (const float4*)w_dcn;     // [64][144] of float4
    const float4* c4 = (const float4*)colsT;     // [576][8]  of float4
    const int obase = og * 4;

    #pragma unroll 2
    for (int ii = 0; ii < CK; ii += 4) {
        float4 cv[4];
        float4 wv[4];
        #pragma unroll
        for (int r = 0; r < 4; r++) cv[r] = c4[(ii + r) * 8 + pg];
        #pragma unroll
        for (int oo = 0; oo < 4; oo++) wv[oo] = __ldg(w4 + (obase + oo) * 144 + (ii >> 2));
        #pragma unroll
        for (int oo = 0; oo < 4; oo++) {
            acc[oo][0] += wv[oo].x * cv[0].x + wv[oo].y * cv[1].x + wv[oo].z * cv[2].x + wv[oo].w * cv[3].x;
            acc[oo][1] += wv[oo].x * cv[0].y + wv[oo].y * cv[1].y + wv[oo].z * cv[2].y + wv[oo].w * cv[3].y;
            acc[oo][2] += wv[oo].x * cv[0].z + wv[oo].y * cv[1].z + wv[oo].z * cv[2].z + wv[oo].w * cv[3].z;
            acc[oo][3] += wv[oo].x * cv[0].w + wv[oo].y * cv[1].w + wv[oo].z * cv[2].w + wv[oo].w * cv[3].w;
        }
    }

    // Epilogue: BN affine + ReLU, vectorized store (4 consecutive pixels)
    const int pbase = h * W_ + w0 + 4 * pg;
    #pragma unroll
    for (int oo = 0; oo < 4; oo++) {
        const int o = obase + oo;
        const float s  = scale_s[o];
        const float sh = shift_s[o];
        float4 r;
        r.x = fmaxf(acc[oo][0] * s + sh, 0.0f);
        r.y = fmaxf(acc[oo][1] * s + sh, 0.0f);
        r.z = fmaxf(acc[oo][2] * s + sh, 0.0f);
        r.w = fmaxf(acc[oo][3] * s + sh, 0.0f);
        *(float4*)(out + (b * O_ + o) * HW_ + pbase) = r;
    }
}

// ---------------------------------------------------------------------------
extern "C" void kernel_launch(void* const* d_in, const int* in_sizes, int n_in,
                              void* d_out, int out_size)
{
    const float* x        = (const float*)d_in[0];
    const float* w_off    = (const float*)d_in[1];
    const float* b_off    = (const float*)d_in[2];
    const float* w_dcn    = (const float*)d_in[3];
    const float* b_dcn    = (const float*)d_in[4];
    const float* gamma    = (const float*)d_in[5];
    const float* beta     = (const float*)d_in[6];
    const float* run_mean = (const float*)d_in[7];
    const float* run_var  = (const float*)d_in[8];
    float* out = (float*)d_out;

    const int smem1 = CK * PIX * sizeof(float);                  // 73728
    const int smem2 = (CK * PIX + 2304 + 128) * sizeof(float);   // 83456

    cudaFuncSetAttribute(offset_conv_kernel,
                         cudaFuncAttributeMaxDynamicSharedMemorySize, smem1);
    cudaFuncSetAttribute(deform_main_kernel,
                         cudaFuncAttributeMaxDynamicSharedMemorySize, smem2);

    dim3 grid(W_ / PIX, H_, B_);   // 5 x 160 x 8 = 6400 blocks

    offset_conv_kernel<<<grid, 144, smem1>>>(x, w_off, b_off);
    deform_main_kernel<<<grid, 128, smem2>>>(x, w_dcn, b_dcn, gamma, beta,
                                             run_mean, run_var, out);
}

// round 7
// speedup vs baseline: 1.6416x; 1.6416x over previous
#include <cuda_runtime.h>

#define B_  8
#define C_  64
#define O_  64
#define H_  160
#define W_  160
#define HW_ (H_*W_)
#define OCOFF 18
#define CK  576      // C_ * 9
#define PIX 32

// Main kernel K-chunking: 8 channels -> 72 K-rows per chunk
#define MCH_C    8
#define MCH_ROWS 72
#define N_MCH    (C_ / MCH_C)      // 8 chunks

// Offset kernel K-chunking: 16 channels -> 144 K-rows per chunk
#define OCH_C    16
#define OCH_ROWS 144
#define N_OCH    (C_ / OCH_C)      // 4 chunks

// Scratch for the offset feature map [B,18,H,W]
__device__ float g_offset[B_ * OCOFF * HW_];

// ---------------------------------------------------------------------------
// Kernel 1: 3x3 offset conv (pad 1): x[B,64,H,W] -> g_offset[B,18,H,W]
// Block: 144 threads, 32-pixel row tile, K chunked into 4 x 144 rows.
// smem 18.4 KB -> ~10 CTAs/SM resident (was 3).
// ---------------------------------------------------------------------------
__global__ __launch_bounds__(144) void offset_conv_kernel(
    const float* __restrict__ x,
    const float* __restrict__ w_off,
    const float* __restrict__ b_off)
{
    __shared__ float colsT[OCH_ROWS * PIX];     // [144][32] = 18432 B

    const int b  = blockIdx.z;
    const int h  = blockIdx.y;
    const int w0 = blockIdx.x * PIX;
    const int tid = threadIdx.x;

    const int og = tid / 16;        // 0..8  -> o in {2og, 2og+1}
    const int pg = tid - og * 16;   // 0..15 -> p in {2pg, 2pg+1}

    float a00 = 0.f, a01 = 0.f, a10 = 0.f, a11 = 0.f;
    const float4* w4 = (const float4*)w_off;    // [18][144] of float4
    const float2* c2 = (const float2*)colsT;    // [144][16] of float2

    for (int ch = 0; ch < N_OCH; ch++) {
        const int c0 = ch * OCH_C;
        // im2col chunk: colsT[cl*9+k][p] = x[b,c0+cl,h+ky-1,w0+p+kx-1]
        for (int j = tid; j < OCH_ROWS * PIX; j += 144) {
            const int p   = j & 31;
            const int idx = j >> 5;            // local row 0..143
            const int cl  = idx / 9;
            const int k   = idx - cl * 9;
            const int row = h + (k / 3) - 1;
            const int col = w0 + p + (k % 3) - 1;
            float v = 0.0f;
            if (row >= 0 && row < H_ && col >= 0 && col < W_)
                v = __ldg(x + (b * C_ + c0 + cl) * HW_ + row * W_ + col);
            colsT[idx * PIX + p] = v;
        }
        __syncthreads();

        const int wbase = ch * 36;             // chunk offset in float4 units
        #pragma unroll 4
        for (int ii = 0; ii < OCH_ROWS; ii += 4) {
            const float2 cv0 = c2[(ii + 0) * 16 + pg];
            const float2 cv1 = c2[(ii + 1) * 16 + pg];
            const float2 cv2 = c2[(ii + 2) * 16 + pg];
            const float2 cv3 = c2[(ii + 3) * 16 + pg];
            const float4 wa = __ldg(w4 + (2 * og + 0) * 144 + wbase + (ii >> 2));
            const float4 wb = __ldg(w4 + (2 * og + 1) * 144 + wbase + (ii >> 2));
            a00 += wa.x * cv0.x + wa.y * cv1.x + wa.z * cv2.x + wa.w * cv3.x;
            a01 += wa.x * cv0.y + wa.y * cv1.y + wa.z * cv2.y + wa.w * cv3.y;
            a10 += wb.x * cv0.x + wb.y * cv1.x + wb.z * cv2.x + wb.w * cv3.x;
            a11 += wb.x * cv0.y + wb.y * cv1.y + wb.z * cv2.y + wb.w * cv3.y;
        }
        __syncthreads();
    }

    const int o0 = 2 * og, o1 = 2 * og + 1;
    const float b0 = __ldg(b_off + o0);
    const float b1 = __ldg(b_off + o1);
    const int pbase = h * W_ + w0 + 2 * pg;
    float2 r0, r1;
    r0.x = a00 + b0; r0.y = a01 + b0;
    r1.x = a10 + b1; r1.y = a11 + b1;
    *(float2*)(&g_offset[(b * OCOFF + o0) * HW_ + pbase]) = r0;
    *(float2*)(&g_offset[(b * OCOFF + o1) * HW_ + pbase]) = r1;
}

// ---------------------------------------------------------------------------
// Kernel 2: deform sample + implicit GEMM (O=64, K=576 chunked) + BN + ReLU.
// Block: 128 threads, 32-pixel tile, K chunked into 8 x 72 rows.
// smem ~19 KB -> 8 CTAs/SM resident (reg-limited), was 2.
// ---------------------------------------------------------------------------
__global__ __launch_bounds__(128) void deform_main_kernel(
    const float* __restrict__ x,
    const float* __restrict__ w_dcn,
    const float* __restrict__ b_dcn,
    const float* __restrict__ gamma,
    const float* __restrict__ beta,
    const float* __restrict__ run_mean,
    const float* __restrict__ run_var,
    float* __restrict__ out)
{
    __shared__ float  buf[MCH_ROWS * PIX];   // [72][32] = 9216 B
    __shared__ int4   idx4[9 * PIX];         // 4608 B
    __shared__ float4 wt4[9 * PIX];          // 4608 B
    __shared__ float  scale_s[O_];
    __shared__ float  shift_s[O_];

    const int b  = blockIdx.z;
    const int h  = blockIdx.y;
    const int w0 = blockIdx.x * PIX;
    const int tid = threadIdx.x;

    // BN scale/shift (b_dcn folded in)
    if (tid < 64) {
        const float inv = __ldg(gamma + tid) * rsqrtf(__ldg(run_var + tid) + 1e-5f);
        scale_s[tid] = inv;
        shift_s[tid] = __ldg(beta + tid) + (__ldg(b_dcn + tid) - __ldg(run_mean + tid)) * inv;
    }

    // Tap metadata for 32 pixels x 9 kernel positions (computed once)
    for (int j = tid; j < 9 * PIX; j += 128) {
        const int k = j >> 5;
        const int p = j & 31;
        const float offy = g_offset[(b * OCOFF + 2 * k)     * HW_ + h * W_ + w0 + p];
        const float offx = g_offset[(b * OCOFF + 2 * k + 1) * HW_ + h * W_ + w0 + p];
        const float py = (float)(h + k / 3 - 1) + offy;
        const float px = (float)(w0 + p + (k % 3) - 1) + offx;
        const float y0f = floorf(py);
        const float x0f = floorf(px);
        const float fy = py - y0f;
        const float fx = px - x0f;
        const int iy0 = (int)y0f, iy1 = iy0 + 1;
        const int ix0 = (int)x0f, ix1 = ix0 + 1;
        const bool vy0 = (iy0 >= 0) && (iy0 < H_);
        const bool vy1 = (iy1 >= 0) && (iy1 < H_);
        const bool vx0 = (ix0 >= 0) && (ix0 < W_);
        const bool vx1 = (ix1 >= 0) && (ix1 < W_);
        const float wy0 = 1.0f - fy, wy1 = fy;
        const float wx0 = 1.0f - fx, wx1 = fx;
        float4 wv;
        wv.x = (vy0 && vx0) ? wy0 * wx0 : 0.0f;
        wv.y = (vy0 && vx1) ? wy0 * wx1 : 0.0f;
        wv.z = (vy1 && vx0) ? wy1 * wx0 : 0.0f;
        wv.w = (vy1 && vx1) ? wy1 * wx1 : 0.0f;
        wt4[j] = wv;
        const int iy0c = min(max(iy0, 0), H_ - 1);
        const int iy1c = min(max(iy1, 0), H_ - 1);
        const int ix0c = min(max(ix0, 0), W_ - 1);
        const int ix1c = min(max(ix1, 0), W_ - 1);
        int4 ia;
        ia.x = iy0c * W_ + ix0c;
        ia.y = iy0c * W_ + ix1c;
        ia.z = iy1c * W_ + ix0c;
        ia.w = iy1c * W_ + ix1c;
        idx4[j] = ia;
    }
    __syncthreads();

    const int og = tid >> 3;        // 0..15 -> o base = 4*og
    const int pg = tid & 7;         // 0..7  -> p base = 4*pg
    const int p  = tid & 31;        // sampling lane = pixel
    const int cg = tid >> 5;        // 0..3 channel group

    float acc[4][4];
    #pragma unroll
    for (int i = 0; i < 4; i++)
        #pragma unroll
        for (int jj = 0; jj < 4; jj++) acc[i][jj] = 0.0f;

    const float4* w4 = (const float4*)w_dcn;     // [64][144] of float4
    const float4* c4 = (const float4*)buf;       // [72][8]   of float4
    const int obase = og * 4;
    const float* xb = x + b * C_ * HW_;

    for (int ch = 0; ch < N_MCH; ch++) {
        const int c0 = ch * MCH_C;

        // ---- sample 8 channels x 9 taps x 32 pixels into buf[cl*9+k][p]
        #pragma unroll
        for (int k = 0; k < 9; k++) {
            const int j = k * 32 + p;
            const int4  ia = idx4[j];
            const float4 wv = wt4[j];
            #pragma unroll
            for (int cl = cg; cl < MCH_C; cl += 4) {    // 2 iterations
                const float* xc = xb + (c0 + cl) * HW_;
                const float v = wv.x * __ldg(xc + ia.x) + wv.y * __ldg(xc + ia.y)
                              + wv.z * __ldg(xc + ia.z) + wv.w * __ldg(xc + ia.w);
                buf[(cl * 9 + k) * PIX + p] = v;
            }
        }
        __syncthreads();

        // ---- GEMM accumulate over this K-slice (72 rows)
        const int wbase = ch * 18;                      // float4 units
        #pragma unroll 2
        for (int ii = 0; ii < MCH_ROWS; ii += 4) {
            float4 cv[4];
            float4 wv[4];
            #pragma unroll
            for (int r = 0; r < 4; r++) cv[r] = c4[(ii + r) * 8 + pg];
            #pragma unroll
            for (int oo = 0; oo < 4; oo++)
                wv[oo] = __ldg(w4 + (obase + oo) * 144 + wbase + (ii >> 2));
            #pragma unroll
            for (int oo = 0; oo < 4; oo++) {
                acc[oo][0] += wv[oo].x * cv[0].x + wv[oo].y * cv[1].x + wv[oo].z * cv[2].x + wv[oo].w * cv[3].x;
                acc[oo][1] += wv[oo].x * cv[0].y + wv[oo].y * cv[1].y + wv[oo].z * cv[2].y + wv[oo].w * cv[3].y;
                acc[oo][2] += wv[oo].x * cv[0].z + wv[oo].y * cv[1].z + wv[oo].z * cv[2].z + wv[oo].w * cv[3].z;
                acc[oo][3] += wv[oo].x * cv[0].w + wv[oo].y * cv[1].w + wv[oo].z * cv[2].w + wv[oo].w * cv[3].w;
            }
        }
        __syncthreads();
    }

    // Epilogue: BN affine + ReLU, vectorized store (4 consecutive pixels)
    const int pbase = h * W_ + w0 + 4 * pg;
    #pragma unroll
    for (int oo = 0; oo < 4; oo++) {
        const int o = obase + oo;
        const float s  = scale_s[o];
        const float sh = shift_s[o];
        float4 r;
        r.x = fmaxf(acc[oo][0] * s + sh, 0.0f);
        r.y = fmaxf(acc[oo][1] * s + sh, 0.0f);
        r.z = fmaxf(acc[oo][2] * s + sh, 0.0f);
        r.w = fmaxf(acc[oo][3] * s + sh, 0.0f);
        *(float4*)(out + (b * O_ + o) * HW_ + pbase) = r;
    }
}

// ---------------------------------------------------------------------------
extern "C" void kernel_launch(void* const* d_in, const int* in_sizes, int n_in,
                              void* d_out, int out_size)
{
    const float* x        = (const float*)d_in[0];
    const float* w_off    = (const float*)d_in[1];
    const float* b_off    = (const float*)d_in[2];
    const float* w_dcn    = (const float*)d_in[3];
    const float* b_dcn    = (const float*)d_in[4];
    const float* gamma    = (const float*)d_in[5];
    const float* beta     = (const float*)d_in[6];
    const float* run_mean = (const float*)d_in[7];
    const float* run_var  = (const float*)d_in[8];
    float* out = (float*)d_out;

    dim3 grid(W_ / PIX, H_, B_);   // 5 x 160 x 8 = 6400 blocks

    offset_conv_kernel<<<grid, 144>>>(x, w_off, b_off);
    deform_main_kernel<<<grid, 128>>>(x, w_dcn, b_dcn, gamma, beta,
                                      run_mean, run_var, out);
}

// round 8
// speedup vs baseline: 1.7532x; 1.0680x over previous
#include <cuda_runtime.h>

#define B_  8
#define C_  64
#define O_  64
#define H_  160
#define W_  160
#define HW_ (H_*W_)
#define OCOFF 18
#define CK  576      // C_ * 9
#define PIX 32

// Main kernel K-chunking: 16 channels -> 144 K-rows per chunk, 4 chunks
#define MCH_C    16
#define MCH_ROWS 144
#define N_MCH    (C_ / MCH_C)      // 4 chunks

// Offset kernel K-chunking: 8 channels -> 72 K-rows per chunk, 8 chunks
#define OCH_C    8
#define OCH_ROWS 72
#define N_OCH    (C_ / OCH_C)      // 8 chunks
#define OPIX 64                    // 2 rows x 32 pixels

// Scratch for the offset feature map [B,18,H,W]
__device__ float g_offset[B_ * OCOFF * HW_];

// ---------------------------------------------------------------------------
// Kernel 1: 3x3 offset conv (pad 1): x[B,64,H,W] -> g_offset[B,18,H,W]
// Block: 144 threads, 2-row x 32-pixel tile (64 px), 2o x 4p register tile.
// K chunked into 8 x 72 rows (18.4 KB smem).
// ---------------------------------------------------------------------------
__global__ __launch_bounds__(144) void offset_conv_kernel(
    const float* __restrict__ x,
    const float* __restrict__ w_off,
    const float* __restrict__ b_off)
{
    __shared__ float colsT[OCH_ROWS * OPIX];     // [72][64] = 18432 B

    const int b  = blockIdx.z;
    const int h0 = blockIdx.y * 2;
    const int w0 = blockIdx.x * PIX;
    const int tid = threadIdx.x;

    const int og = tid / 16;        // 0..8  -> o in {2og, 2og+1}
    const int pg = tid - og * 16;   // 0..15 -> 4 px starting at 4*pg (cp space)

    float acc[2][4];
    #pragma unroll
    for (int i = 0; i < 2; i++)
        #pragma unroll
        for (int jj = 0; jj < 4; jj++) acc[i][jj] = 0.0f;

    const float4* w4 = (const float4*)w_off;    // [18][144] of float4
    const float4* c4 = (const float4*)colsT;    // [72][16]  of float4

    for (int ch = 0; ch < N_OCH; ch++) {
        const int c0 = ch * OCH_C;
        // im2col chunk: colsT[(cl*9+k)][cp], cp = r*32+p -> pixel (h0+r, w0+p)
        for (int j = tid; j < OCH_ROWS * OPIX; j += 144) {
            const int cp  = j & 63;
            const int idx = j >> 6;            // local row 0..71
            const int cl  = idx / 9;
            const int k   = idx - cl * 9;
            const int r   = cp >> 5;
            const int p   = cp & 31;
            const int row = h0 + r + (k / 3) - 1;
            const int col = w0 + p + (k % 3) - 1;
            float v = 0.0f;
            if (row >= 0 && row < H_ && col >= 0 && col < W_)
                v = __ldg(x + (b * C_ + c0 + cl) * HW_ + row * W_ + col);
            colsT[idx * OPIX + cp] = v;
        }
        __syncthreads();

        const int wbase = ch * 18;             // chunk offset in float4 units
        #pragma unroll 2
        for (int ii = 0; ii < OCH_ROWS; ii += 4) {
            float4 cv[4];
            #pragma unroll
            for (int r = 0; r < 4; r++) cv[r] = c4[(ii + r) * 16 + pg];
            const float4 wa = __ldg(w4 + (2 * og + 0) * 144 + wbase + (ii >> 2));
            const float4 wb = __ldg(w4 + (2 * og + 1) * 144 + wbase + (ii >> 2));
            #pragma unroll
            for (int q = 0; q < 4; q++) {
                const float c0v = (&cv[0].x)[q];
                const float c1v = (&cv[1].x)[q];
                const float c2v = (&cv[2].x)[q];
                const float c3v = (&cv[3].x)[q];
                acc[0][q] += wa.x * c0v + wa.y * c1v + wa.z * c2v + wa.w * c3v;
                acc[1][q] += wb.x * c0v + wb.y * c1v + wb.z * c2v + wb.w * c3v;
            }
        }
        __syncthreads();
    }

    const int o0 = 2 * og, o1 = 2 * og + 1;
    const float b0 = __ldg(b_off + o0);
    const float b1 = __ldg(b_off + o1);
    const int r   = pg >> 3;                    // 4*pg >= 32 ? 1 : 0
    const int col = (4 * pg) & 31;
    const int pbase = (h0 + r) * W_ + w0 + col;
    float4 r0, r1;
    r0.x = acc[0][0] + b0; r0.y = acc[0][1] + b0; r0.z = acc[0][2] + b0; r0.w = acc[0][3] + b0;
    r1.x = acc[1][0] + b1; r1.y = acc[1][1] + b1; r1.z = acc[1][2] + b1; r1.w = acc[1][3] + b1;
    *(float4*)(&g_offset[(b * OCOFF + o0) * HW_ + pbase]) = r0;
    *(float4*)(&g_offset[(b * OCOFF + o1) * HW_ + pbase]) = r1;
}

// ---------------------------------------------------------------------------
// Kernel 2: deform sample + implicit GEMM (O=64, K=576, 4 x 144-row chunks)
// + BN + ReLU. Block: 128 threads, 32-pixel tile.
// Metadata: packed int (base|dx<<15|dy<<16) + separable masked weights.
// ---------------------------------------------------------------------------
__global__ __launch_bounds__(128) void deform_main_kernel(
    const float* __restrict__ x,
    const float* __restrict__ w_dcn,
    const float* __restrict__ b_dcn,
    const float* __restrict__ gamma,
    const float* __restrict__ beta,
    const float* __restrict__ run_mean,
    const float* __restrict__ run_var,
    float* __restrict__ out)
{
    __shared__ float  buf[MCH_ROWS * PIX];   // [144][32] = 18432 B
    __shared__ int    idxp[9 * PIX];         // 1152 B (packed)
    __shared__ float4 wt4[9 * PIX];          // 4608 B (wy0',wy1',wx0',wx1')
    __shared__ float  scale_s[O_];
    __shared__ float  shift_s[O_];

    const int b  = blockIdx.z;
    const int h  = blockIdx.y;
    const int w0 = blockIdx.x * PIX;
    const int tid = threadIdx.x;

    // BN scale/shift (b_dcn folded in)
    if (tid < 64) {
        const float inv = __ldg(gamma + tid) * rsqrtf(__ldg(run_var + tid) + 1e-5f);
        scale_s[tid] = inv;
        shift_s[tid] = __ldg(beta + tid) + (__ldg(b_dcn + tid) - __ldg(run_mean + tid)) * inv;
    }

    // Tap metadata for 32 pixels x 9 kernel positions (computed once)
    for (int j = tid; j < 9 * PIX; j += 128) {
        const int k = j >> 5;
        const int p = j & 31;
        const float offy = g_offset[(b * OCOFF + 2 * k)     * HW_ + h * W_ + w0 + p];
        const float offx = g_offset[(b * OCOFF + 2 * k + 1) * HW_ + h * W_ + w0 + p];
        const float py = (float)(h + k / 3 - 1) + offy;
        const float px = (float)(w0 + p + (k % 3) - 1) + offx;
        const float y0f = floorf(py);
        const float x0f = floorf(px);
        const float fy = py - y0f;
        const float fx = px - x0f;
        const int iy0 = (int)y0f, iy1 = iy0 + 1;
        const int ix0 = (int)x0f, ix1 = ix0 + 1;
        const bool vy0 = (iy0 >= 0) && (iy0 < H_);
        const bool vy1 = (iy1 >= 0) && (iy1 < H_);
        const bool vx0 = (ix0 >= 0) && (ix0 < W_);
        const bool vx1 = (ix1 >= 0) && (ix1 < W_);
        // separable masked weights: w_ab = wy_a' * wx_b'
        float4 wv;
        wv.x = vy0 ? (1.0f - fy) : 0.0f;   // wy0'
        wv.y = vy1 ? fy          : 0.0f;   // wy1'
        wv.z = vx0 ? (1.0f - fx) : 0.0f;   // wx0'
        wv.w = vx1 ? fx          : 0.0f;   // wx1'
        wt4[j] = wv;
        const int iy0c = min(max(iy0, 0), H_ - 1);
        const int iy1c = min(max(iy1, 0), H_ - 1);
        const int ix0c = min(max(ix0, 0), W_ - 1);
        const int ix1c = min(max(ix1, 0), W_ - 1);
        const int base = iy0c * W_ + ix0c;           // <= 25599, fits 15 bits
        const int dx   = ix1c - ix0c;                // 0 or 1
        const int dy   = iy1c - iy0c;                // 0 or 1
        idxp[j] = base | (dx << 15) | (dy << 16);
    }
    __syncthreads();

    const int og = tid >> 3;        // 0..15 -> o base = 4*og
    const int pg = tid & 7;         // 0..7  -> p base = 4*pg
    const int p  = tid & 31;        // sampling lane = pixel
    const int cg = tid >> 5;        // 0..3 channel group

    float acc[4][4];
    #pragma unroll
    for (int i = 0; i < 4; i++)
        #pragma unroll
        for (int jj = 0; jj < 4; jj++) acc[i][jj] = 0.0f;

    const float4* w4 = (const float4*)w_dcn;     // [64][144] of float4
    const float4* c4 = (const float4*)buf;       // [144][8]  of float4
    const int obase = og * 4;
    const float* xb = x + b * C_ * HW_;

    for (int ch = 0; ch < N_MCH; ch++) {
        const int c0 = ch * MCH_C;

        // ---- sample 16 channels x 9 taps x 32 pixels into buf[cl*9+k][p]
        #pragma unroll
        for (int k = 0; k < 9; k++) {
            const int j = k * 32 + p;
            const int   pk = idxp[j];
            const float4 wv = wt4[j];
            const int base = pk & 0x7FFF;
            const int dx   = (pk >> 15) & 1;
            const int dW   = ((pk >> 16) & 1) * W_;
            const int i00 = base;
            const int i01 = base + dx;
            const int i10 = base + dW;
            const int i11 = i10 + dx;
            #pragma unroll
            for (int cl = cg; cl < MCH_C; cl += 4) {    // 4 iterations
                const float* xc = xb + (c0 + cl) * HW_;
                const float g00 = __ldg(xc + i00);
                const float g01 = __ldg(xc + i01);
                const float g10 = __ldg(xc + i10);
                const float g11 = __ldg(xc + i11);
                const float v = wv.x * (wv.z * g00 + wv.w * g01)
                              + wv.y * (wv.z * g10 + wv.w * g11);
                buf[(cl * 9 + k) * PIX + p] = v;
            }
        }
        __syncthreads();

        // ---- GEMM accumulate over this K-slice (144 rows)
        const int wbase = ch * 36;                      // float4 units
        #pragma unroll 2
        for (int ii = 0; ii < MCH_ROWS; ii += 4) {
            float4 cv[4];
            float4 wv[4];
            #pragma unroll
            for (int r = 0; r < 4; r++) cv[r] = c4[(ii + r) * 8 + pg];
            #pragma unroll
            for (int oo = 0; oo < 4; oo++)
                wv[oo] = __ldg(w4 + (obase + oo) * 144 + wbase + (ii >> 2));
            #pragma unroll
            for (int oo = 0; oo < 4; oo++) {
                acc[oo][0] += wv[oo].x * cv[0].x + wv[oo].y * cv[1].x + wv[oo].z * cv[2].x + wv[oo].w * cv[3].x;
                acc[oo][1] += wv[oo].x * cv[0].y + wv[oo].y * cv[1].y + wv[oo].z * cv[2].y + wv[oo].w * cv[3].y;
                acc[oo][2] += wv[oo].x * cv[0].z + wv[oo].y * cv[1].z + wv[oo].z * cv[2].z + wv[oo].w * cv[3].z;
                acc[oo][3] += wv[oo].x * cv[0].w + wv[oo].y * cv[1].w + wv[oo].z * cv[2].w + wv[oo].w * cv[3].w;
            }
        }
        __syncthreads();
    }

    // Epilogue: BN affine + ReLU, vectorized store (4 consecutive pixels)
    const int pbase = h * W_ + w0 + 4 * pg;
    #pragma unroll
    for (int oo = 0; oo < 4; oo++) {
        const int o = obase + oo;
        const float s  = scale_s[o];
        const float sh = shift_s[o];
        float4 r;
        r.x = fmaxf(acc[oo][0] * s + sh, 0.0f);
        r.y = fmaxf(acc[oo][1] * s + sh, 0.0f);
        r.z = fmaxf(acc[oo][2] * s + sh, 0.0f);
        r.w = fmaxf(acc[oo][3] * s + sh, 0.0f);
        *(float4*)(out + (b * O_ + o) * HW_ + pbase) = r;
    }
}

// ---------------------------------------------------------------------------
extern "C" void kernel_launch(void* const* d_in, const int* in_sizes, int n_in,
                              void* d_out, int out_size)
{
    const float* x        = (const float*)d_in[0];
    const float* w_off    = (const float*)d_in[1];
    const float* b_off    = (const float*)d_in[2];
    const float* w_dcn    = (const float*)d_in[3];
    const float* b_dcn    = (const float*)d_in[4];
    const float* gamma    = (const float*)d_in[5];
    const float* beta     = (const float*)d_in[6];
    const float* run_mean = (const float*)d_in[7];
    const float* run_var  = (const float*)d_in[8];
    float* out = (float*)d_out;

    dim3 grid_off(W_ / PIX, H_ / 2, B_);   // 5 x 80 x 8
    dim3 grid_main(W_ / PIX, H_, B_);      // 5 x 160 x 8

    offset_conv_kernel<<<grid_off, 144>>>(x, w_off, b_off);
    deform_main_kernel<<<grid_main, 128>>>(x, w_dcn, b_dcn, gamma, beta,
                                           run_mean, run_var, out);
}

// round 9
// speedup vs baseline: 1.8697x; 1.0664x over previous
#include <cuda_runtime.h>

#define B_  8
#define C_  64
#define O_  64
#define H_  160
#define W_  160
#define HW_ (H_*W_)
#define OCOFF 18
#define CK  576      // C_ * 9
#define PIX 32

// K-chunking: 16 channels -> 144 K-rows per chunk, 4 chunks
#define MCH_C    16
#define MCH_ROWS 144
#define N_MCH    (C_ / MCH_C)      // 4 chunks

// ---------------------------------------------------------------------------
// Fused kernel: offset conv (18ch) + deform sample + implicit GEMM (O=64,
// K=576, 4 x 144-row chunks) + BN + ReLU. Block: 128 threads, 32-pixel tile.
// Phases:
//   1. chunked im2col + 18x32 offset GEMM (accumulated in regs)
//   2. offsets -> smem
//   3. tap metadata (packed idx + separable masked weights)
//   4. chunked bilinear sampling + 64x32 main GEMM (R8 structure)
// ---------------------------------------------------------------------------
__global__ __launch_bounds__(128) void fused_deform_kernel(
    const float* __restrict__ x,
    const float* __restrict__ w_off,
    const float* __restrict__ b_off,
    const float* __restrict__ w_dcn,
    const float* __restrict__ b_dcn,
    const float* __restrict__ gamma,
    const float* __restrict__ beta,
    const float* __restrict__ run_mean,
    const float* __restrict__ run_var,
    float* __restrict__ out)
{
    __shared__ float  buf[MCH_ROWS * PIX];   // [144][32] = 18432 B (im2col / cols)
    __shared__ int    idxp[9 * PIX];         // 1152 B (packed indices)
    __shared__ float4 wt4[9 * PIX];          // 4608 B (wy0',wy1',wx0',wx1')
    __shared__ float  off_s[OCOFF * PIX];    // 2304 B (offset tile)
    __shared__ float  scale_s[O_];
    __shared__ float  shift_s[O_];

    const int b  = blockIdx.z;
    const int h  = blockIdx.y;
    const int w0 = blockIdx.x * PIX;
    const int tid = threadIdx.x;

    // ---- Phase 0: BN scale/shift (b_dcn folded in)
    if (tid < 64) {
        const float inv = __ldg(gamma + tid) * rsqrtf(__ldg(run_var + tid) + 1e-5f);
        scale_s[tid] = inv;
        shift_s[tid] = __ldg(beta + tid) + (__ldg(b_dcn + tid) - __ldg(run_mean + tid)) * inv;
    }

    // ---- Phase 1: offset conv, chunked im2col + register-tiled GEMM
    // Thread (og1, pg1): o in {og1, og1+8} (+ {16+og1} if og1<2), p in {2pg1, 2pg1+1}
    const int og1 = tid >> 4;       // 0..7
    const int pg1 = tid & 15;       // 0..15

    float oa0[2] = {0.f, 0.f};
    float oa1[2] = {0.f, 0.f};
    float oa2[2] = {0.f, 0.f};

    const float4* wo4 = (const float4*)w_off;   // [18][144] of float4
    const float2* c2  = (const float2*)buf;     // [144][16] of float2
    const float*  xb  = x + b * C_ * HW_;

    for (int ch = 0; ch < N_MCH; ch++) {
        const int c0 = ch * MCH_C;
        // im2col chunk: buf[cl*9+k][p] = x[b,c0+cl,h+ky-1,w0+p+kx-1]
        for (int j = tid; j < MCH_ROWS * PIX; j += 128) {
            const int p   = j & 31;
            const int idx = j >> 5;            // local row 0..143
            const int cl  = idx / 9;
            const int k   = idx - cl * 9;
            const int row = h + (k / 3) - 1;
            const int col = w0 + p + (k % 3) - 1;
            float v = 0.0f;
            if (row >= 0 && row < H_ && col >= 0 && col < W_)
                v = __ldg(xb + (c0 + cl) * HW_ + row * W_ + col);
            buf[idx * PIX + p] = v;
        }
        __syncthreads();

        const int wbase = ch * 36;             // chunk offset in float4 units
        #pragma unroll 4
        for (int ii = 0; ii < MCH_ROWS; ii += 4) {
            const float2 cv0 = c2[(ii + 0) * 16 + pg1];
            const float2 cv1 = c2[(ii + 1) * 16 + pg1];
            const float2 cv2 = c2[(ii + 2) * 16 + pg1];
            const float2 cv3 = c2[(ii + 3) * 16 + pg1];
            const float4 wa = __ldg(wo4 + (og1 + 0) * 144 + wbase + (ii >> 2));
            const float4 wb = __ldg(wo4 + (og1 + 8) * 144 + wbase + (ii >> 2));
            oa0[0] += wa.x * cv0.x + wa.y * cv1.x + wa.z * cv2.x + wa.w * cv3.x;
            oa0[1] += wa.x * cv0.y + wa.y * cv1.y + wa.z * cv2.y + wa.w * cv3.y;
            oa1[0] += wb.x * cv0.x + wb.y * cv1.x + wb.z * cv2.x + wb.w * cv3.x;
            oa1[1] += wb.x * cv0.y + wb.y * cv1.y + wb.z * cv2.y + wb.w * cv3.y;
            if (og1 < 2) {
                const float4 wc = __ldg(wo4 + (16 + og1) * 144 + wbase + (ii >> 2));
                oa2[0] += wc.x * cv0.x + wc.y * cv1.x + wc.z * cv2.x + wc.w * cv3.x;
                oa2[1] += wc.x * cv0.y + wc.y * cv1.y + wc.z * cv2.y + wc.w * cv3.y;
            }
        }
        __syncthreads();
    }

    // ---- Phase 2: offsets to smem (+ bias)
    {
        const int p0 = 2 * pg1;
        const float bb0 = __ldg(b_off + og1);
        const float bb1 = __ldg(b_off + og1 + 8);
        off_s[(og1 + 0) * PIX + p0]     = oa0[0] + bb0;
        off_s[(og1 + 0) * PIX + p0 + 1] = oa0[1] + bb0;
        off_s[(og1 + 8) * PIX + p0]     = oa1[0] + bb1;
        off_s[(og1 + 8) * PIX + p0 + 1] = oa1[1] + bb1;
        if (og1 < 2) {
            const float bb2 = __ldg(b_off + 16 + og1);
            off_s[(16 + og1) * PIX + p0]     = oa2[0] + bb2;
            off_s[(16 + og1) * PIX + p0 + 1] = oa2[1] + bb2;
        }
    }
    __syncthreads();

    // ---- Phase 3: tap metadata for 32 pixels x 9 kernel positions
    for (int j = tid; j < 9 * PIX; j += 128) {
        const int k = j >> 5;
        const int p = j & 31;
        const float offy = off_s[(2 * k)     * PIX + p];
        const float offx = off_s[(2 * k + 1) * PIX + p];
        const float py = (float)(h + k / 3 - 1) + offy;
        const float px = (float)(w0 + p + (k % 3) - 1) + offx;
        const float y0f = floorf(py);
        const float x0f = floorf(px);
        const float fy = py - y0f;
        const float fx = px - x0f;
        const int iy0 = (int)y0f, iy1 = iy0 + 1;
        const int ix0 = (int)x0f, ix1 = ix0 + 1;
        const bool vy0 = (iy0 >= 0) && (iy0 < H_);
        const bool vy1 = (iy1 >= 0) && (iy1 < H_);
        const bool vx0 = (ix0 >= 0) && (ix0 < W_);
        const bool vx1 = (ix1 >= 0) && (ix1 < W_);
        float4 wv;
        wv.x = vy0 ? (1.0f - fy) : 0.0f;   // wy0'
        wv.y = vy1 ? fy          : 0.0f;   // wy1'
        wv.z = vx0 ? (1.0f - fx) : 0.0f;   // wx0'
        wv.w = vx1 ? fx          : 0.0f;   // wx1'
        wt4[j] = wv;
        const int iy0c = min(max(iy0, 0), H_ - 1);
        const int iy1c = min(max(iy1, 0), H_ - 1);
        const int ix0c = min(max(ix0, 0), W_ - 1);
        const int ix1c = min(max(ix1, 0), W_ - 1);
        const int base = iy0c * W_ + ix0c;           // <= 25599, fits 15 bits
        const int dx   = ix1c - ix0c;                // 0 or 1
        const int dy   = iy1c - iy0c;                // 0 or 1
        idxp[j] = base | (dx << 15) | (dy << 16);
    }
    __syncthreads();

    // ---- Phase 4: sampling + main GEMM (R8 structure)
    const int og = tid >> 3;        // 0..15 -> o base = 4*og
    const int pg = tid & 7;         // 0..7  -> p base = 4*pg
    const int p  = tid & 31;        // sampling lane = pixel
    const int cg = tid >> 5;        // 0..3 channel group

    float acc[4][4];
    #pragma unroll
    for (int i = 0; i < 4; i++)
        #pragma unroll
        for (int jj = 0; jj < 4; jj++) acc[i][jj] = 0.0f;

    const float4* w4 = (const float4*)w_dcn;     // [64][144] of float4
    const float4* c4 = (const float4*)buf;       // [144][8]  of float4
    const int obase = og * 4;

    for (int ch = 0; ch < N_MCH; ch++) {
        const int c0 = ch * MCH_C;

        // ---- sample 16 channels x 9 taps x 32 pixels into buf[cl*9+k][p]
        #pragma unroll
        for (int k = 0; k < 9; k++) {
            const int j = k * 32 + p;
            const int   pk = idxp[j];
            const float4 wv = wt4[j];
            const int base = pk & 0x7FFF;
            const int dx   = (pk >> 15) & 1;
            const int dW   = ((pk >> 16) & 1) * W_;
            const int i00 = base;
            const int i01 = base + dx;
            const int i10 = base + dW;
            const int i11 = i10 + dx;
            #pragma unroll
            for (int cl = cg; cl < MCH_C; cl += 4) {    // 4 iterations
                const float* xc = xb + (c0 + cl) * HW_;
                const float g00 = __ldg(xc + i00);
                const float g01 = __ldg(xc + i01);
                const float g10 = __ldg(xc + i10);
                const float g11 = __ldg(xc + i11);
                const float v = wv.x * (wv.z * g00 + wv.w * g01)
                              + wv.y * (wv.z * g10 + wv.w * g11);
                buf[(cl * 9 + k) * PIX + p] = v;
            }
        }
        __syncthreads();

        // ---- GEMM accumulate over this K-slice (144 rows)
        const int wbase = ch * 36;                      // float4 units
        #pragma unroll 2
        for (int ii = 0; ii < MCH_ROWS; ii += 4) {
            float4 cv[4];
            float4 wv[4];
            #pragma unroll
            for (int r = 0; r < 4; r++) cv[r] = c4[(ii + r) * 8 + pg];
            #pragma unroll
            for (int oo = 0; oo < 4; oo++)
                wv[oo] = __ldg(w4 + (obase + oo) * 144 + wbase + (ii >> 2));
            #pragma unroll
            for (int oo = 0; oo < 4; oo++) {
                acc[oo][0] += wv[oo].x * cv[0].x + wv[oo].y * cv[1].x + wv[oo].z * cv[2].x + wv[oo].w * cv[3].x;
                acc[oo][1] += wv[oo].x * cv[0].y + wv[oo].y * cv[1].y + wv[oo].z * cv[2].y + wv[oo].w * cv[3].y;
                acc[oo][2] += wv[oo].x * cv[0].z + wv[oo].y * cv[1].z + wv[oo].z * cv[2].z + wv[oo].w * cv[3].z;
                acc[oo][3] += wv[oo].x * cv[0].w + wv[oo].y * cv[1].w + wv[oo].z * cv[2].w + wv[oo].w * cv[3].w;
            }
        }
        __syncthreads();
    }

    // ---- Epilogue: BN affine + ReLU, vectorized store (4 consecutive pixels)
    const int pbase = h * W_ + w0 + 4 * pg;
    #pragma unroll
    for (int oo = 0; oo < 4; oo++) {
        const int o = obase + oo;
        const float s  = scale_s[o];
        const float sh = shift_s[o];
        float4 r;
        r.x = fmaxf(acc[oo][0] * s + sh, 0.0f);
        r.y = fmaxf(acc[oo][1] * s + sh, 0.0f);
        r.z = fmaxf(acc[oo][2] * s + sh, 0.0f);
        r.w = fmaxf(acc[oo][3] * s + sh, 0.0f);
        *(float4*)(out + (b * O_ + o) * HW_ + pbase) = r;
    }
}

// ---------------------------------------------------------------------------
extern "C" void kernel_launch(void* const* d_in, const int* in_sizes, int n_in,
                              void* d_out, int out_size)
{
    const float* x        = (const float*)d_in[0];
    const float* w_off    = (const float*)d_in[1];
    const float* b_off    = (const float*)d_in[2];
    const float* w_dcn    = (const float*)d_in[3];
    const float* b_dcn    = (const float*)d_in[4];
    const float* gamma    = (const float*)d_in[5];
    const float* beta     = (const float*)d_in[6];
    const float* run_mean = (const float*)d_in[7];
    const float* run_var  = (const float*)d_in[8];
    float* out = (float*)d_out;

    dim3 grid(W_ / PIX, H_, B_);   // 5 x 160 x 8 = 6400 blocks

    fused_deform_kernel<<<grid, 128>>>(x, w_off, b_off, w_dcn, b_dcn,
                                       gamma, beta, run_mean, run_var, out);
}